// round 15
// baseline (speedup 1.0000x reference)
#include <cuda_runtime.h>
#include <cuda_fp16.h>

// APPNP, K=10. State g = norm ⊙ h in fp16 (row = 64 halves = 128B).
//   g_{t+1} = 0.9*norm^2 * (sum_{(s->v)} g_t[s]) + anchor, anchor = 0.1*norm*feat
// Final: h = 0.9*norm*agg + 0.1*feat (fp32).
//
// Round 15: launch-count diet. Per-kernel launch floor measured ~4us (a
// trivial 1-block scan kernel reads 4.5us no matter its internals). The
// counting-sort CSR (deg+scan x3+fill+pad = 6 launches) is replaced by
// fixed-stride buckets: srcs[d*64 + atomicAdd(cnt[d])] = src. No scan at
// all; rowptr == v*64 implicit; per-node {norm, padded_count} packed in one
// int2. Build = 3 kernels (was 8). cnt re-zeroed at end of each call
// (statically zero on call 1) so every call is identical.
// Gather loop = round-8 best, with a 1-load prologue instead of 3.

#define NMAX   100000
#define DF     64
#define DF2    (DF / 2)
#define KITER  10
#define BSTR   64                      // bucket stride (max degree supported)

__device__ uint4 g_a[(NMAX + 1) * 8];
__device__ uint4 g_b[(NMAX + 1) * 8];
__device__ uint4 g_anchor[(NMAX + 1) * 8];  // 0.1*norm*feat in fp16
__device__ int   g_cnt[NMAX];               // statically zero; re-zeroed per call
__device__ int2  g_meta[NMAX];              // {norm bits, padded count}
__device__ int   g_srcs[NMAX * BSTR];       // fixed-stride buckets

// ---------------------------------------------------------------- build ----

// Edge-parallel bucket fill. cnt starts zero (previous call reset it).
__global__ void k_bucket(const int* __restrict__ src,
                         const int* __restrict__ dst, int e) {
    int i = blockIdx.x * blockDim.x + threadIdx.x;
    if (i < e) {
        int d = dst[i];
        int pos = atomicAdd(&g_cnt[d], 1);
        if (pos < BSTR) g_srcs[d * BSTR + pos] = src[i];  // clamp guards OOB
    }
}

// Node-parallel: meta = {norm, dpad}; pad bucket tail to multiple of 4 with
// dummy row n; zero cnt for the next call.
__global__ void k_meta(int n) {
    int i = blockIdx.x * blockDim.x + threadIdx.x;
    if (i < n) {
        int c = g_cnt[i];
        if (c > BSTR) c = BSTR;
        float nm = rsqrtf(fmaxf((float)c, 1.0f));
        int dpad = (c + 3) & ~3;
        g_meta[i] = make_int2(__float_as_int(nm), dpad);
        for (int j = c; j < dpad; ++j) g_srcs[i * BSTR + j] = n;
        g_cnt[i] = 0;
    }
}

// g_a = fp16(norm*feat), anchor = fp16(0.1*norm*feat); zero dummy row n.
__global__ void k_init(const float* __restrict__ feat, int n) {
    int i = blockIdx.x * blockDim.x + threadIdx.x;   // half2 index
    int tot = (n + 1) * DF2;
    if (i >= tot) return;
    __half2* pa = reinterpret_cast<__half2*>(g_a);
    __half2* pb = reinterpret_cast<__half2*>(g_b);
    __half2* pn = reinterpret_cast<__half2*>(g_anchor);
    int row = i >> 5;
    if (row < n) {
        float nm = __int_as_float(g_meta[row].x);
        float2 f = reinterpret_cast<const float2*>(feat)[i];
        pa[i] = __floats2half2_rn(nm * f.x, nm * f.y);
        pn[i] = __floats2half2_rn(0.1f * nm * f.x, 0.1f * nm * f.y);
    } else {
        __half2 z = __floats2half2_rn(0.f, 0.f);
        pa[i] = z; pb[i] = z; pn[i] = z;
    }
}

// ----------------------------------------------------------------- loop ----

__device__ __forceinline__ void acc_row(const uint4& r, float* acc) {
    const __half2* h = reinterpret_cast<const __half2*>(&r);
    #pragma unroll
    for (int j = 0; j < 4; ++j) {
        float2 w = __half22float2(h[j]);
        acc[2 * j]     += w.x;
        acc[2 * j + 1] += w.y;
    }
}

// One warp per node. SIMT-4 gather: one LDG.128 fetches four 128B fp16 rows
// (8 lanes per row). Prologue is a single LDG.64 of {norm, dpad}.
__global__ void __launch_bounds__(256) k_prop(const float* __restrict__ feat,
                       float* __restrict__ out,
                       int n, int flip, int last) {
    int gt   = blockIdx.x * blockDim.x + threadIdx.x;
    int v    = gt >> 5;
    int lane = gt & 31;
    if (v >= n) return;

    const uint4* gin  = flip ? g_b : g_a;
    uint4*       gout = flip ? g_a : g_b;

    int2 m = __ldg(&g_meta[v]);
    float nm = __int_as_float(m.x);
    int idx = v * BSTR;
    int end = idx + m.y;                 // padded: multiple of 4

    int slot = lane >> 3;
    int oct  = lane & 7;

    float acc[8];
    #pragma unroll
    for (int j = 0; j < 8; ++j) acc[j] = 0.f;

    for (; idx + 8 <= end; idx += 8) {
        int s0 = __ldg(&g_srcs[idx + slot]);
        int s1 = __ldg(&g_srcs[idx + 4 + slot]);
        uint4 r0 = gin[s0 * 8 + oct];
        uint4 r1 = gin[s1 * 8 + oct];
        acc_row(r0, acc);
        acc_row(r1, acc);
    }
    if (idx < end) {
        int s0 = __ldg(&g_srcs[idx + slot]);
        uint4 r0 = gin[s0 * 8 + oct];
        acc_row(r0, acc);
    }

    #pragma unroll
    for (int j = 0; j < 8; ++j) {
        acc[j] += __shfl_xor_sync(0xffffffff, acc[j], 8);
        acc[j] += __shfl_xor_sync(0xffffffff, acc[j], 16);
    }

    if (!last) {
        if (lane < 8) {
            float c1 = 0.9f * nm * nm;
            uint4 an = g_anchor[v * 8 + oct];
            const __half2* ah = reinterpret_cast<const __half2*>(&an);
            uint4 o;
            __half2* oh = reinterpret_cast<__half2*>(&o);
            #pragma unroll
            for (int j = 0; j < 4; ++j) {
                float2 a2 = __half22float2(ah[j]);
                oh[j] = __floats2half2_rn(c1 * acc[2 * j]     + a2.x,
                                          c1 * acc[2 * j + 1] + a2.y);
            }
            gout[v * 8 + oct] = o;
        }
    } else {
        if (lane < 8) {
            float c1 = 0.9f * nm;
            const float4* fr = reinterpret_cast<const float4*>(feat + v * DF);
            float4* orow = reinterpret_cast<float4*>(out + v * DF);
            float4 f0 = fr[oct * 2];
            float4 f1 = fr[oct * 2 + 1];
            float4 o0, o1;
            o0.x = c1 * acc[0] + 0.1f * f0.x;
            o0.y = c1 * acc[1] + 0.1f * f0.y;
            o0.z = c1 * acc[2] + 0.1f * f0.z;
            o0.w = c1 * acc[3] + 0.1f * f0.w;
            o1.x = c1 * acc[4] + 0.1f * f1.x;
            o1.y = c1 * acc[5] + 0.1f * f1.y;
            o1.z = c1 * acc[6] + 0.1f * f1.z;
            o1.w = c1 * acc[7] + 0.1f * f1.w;
            orow[oct * 2]     = o0;
            orow[oct * 2 + 1] = o1;
        }
    }
}

// ---------------------------------------------------------------- launch ----

extern "C" void kernel_launch(void* const* d_in, const int* in_sizes, int n_in,
                              void* d_out, int out_size) {
    const float* feat = (const float*)d_in[0];
    const int*   src  = (const int*)d_in[1];
    const int*   dst  = (const int*)d_in[2];
    float*       out  = (float*)d_out;

    int n = in_sizes[0] / DF;   // 100000
    int e = in_sizes[1];        // 1000000

    const int T = 256;
    int blk_e = (e + T - 1) / T;
    int blk_n = (n + T - 1) / T;
    int blk_i = ((n + 1) * DF2 + T - 1) / T;
    int blk_p = (n * 32 + T - 1) / T;       // warp per node

    // Build: 3 kernels (no degree pass, no scan)
    k_bucket<<<blk_e, T>>>(src, dst, e);
    k_meta<<<blk_n, T>>>(n);
    k_init<<<blk_i, T>>>(feat, n);

    // Propagation: ping-pong g_a <-> g_b, final iter writes d_out (fp32).
    for (int t = 0; t < KITER; ++t) {
        int flip = t & 1;
        int last = (t == KITER - 1);
        k_prop<<<blk_p, T>>>(feat, out, n, flip, last);
    }
}